// round 6
// baseline (speedup 1.0000x reference)
#include <cuda_runtime.h>
#include <cstdint>

#define MAX_ATOMS 50000
#define DD 256
#define NB 16

#define BM 128
#define BN 128
#define BK 8
#define NCH (DD / BK)     // 32 K-chunks
#define STG 3             // cp.async pipeline stages
#define RW 12             // smem words per row (8 data + 4 pad; conflict-free)

// Scratch: h = x@W.T+b (row 0 zeroed), and tf32-rounded W.
__device__ float g_h[(size_t)MAX_ATOMS * DD];
__device__ float g_Wr[DD * DD];

// ---------------------------------------------------------------------------
// helpers (sm_80-baseline features only — harness builds plain sm_103 PTX)
// ---------------------------------------------------------------------------
__device__ __forceinline__ uint32_t smem_u32(const void* p) {
    uint32_t a;
    asm("{ .reg .u64 t; cvta.to.shared.u64 t, %1; cvt.u32.u64 %0, t; }" : "=r"(a) : "l"(p));
    return a;
}
__device__ __forceinline__ uint32_t f2tf32(float f) {
    uint32_t u; asm("cvt.rna.tf32.f32 %0, %1;" : "=r"(u) : "f"(f)); return u;
}
__device__ __forceinline__ void ldsm4(uint32_t r[4], uint32_t a) {
    asm volatile("ldmatrix.sync.aligned.m8n8.x4.shared.b16 {%0,%1,%2,%3}, [%4];"
                 : "=r"(r[0]), "=r"(r[1]), "=r"(r[2]), "=r"(r[3]) : "r"(a));
}
__device__ __forceinline__ void cp16(uint32_t dst, const void* src, uint32_t nbytes) {
    asm volatile("cp.async.cg.shared.global [%0], [%1], 16, %2;"
                 :: "r"(dst), "l"(src), "r"(nbytes));
}
__device__ __forceinline__ void mma_tf32(float d[4], const uint32_t a[4],
                                         uint32_t b0, uint32_t b1) {
    asm volatile(
        "mma.sync.aligned.m16n8k8.row.col.f32.tf32.tf32.f32 "
        "{%0,%1,%2,%3}, {%4,%5,%6,%7}, {%8,%9}, {%0,%1,%2,%3};"
        : "+f"(d[0]), "+f"(d[1]), "+f"(d[2]), "+f"(d[3])
        : "r"(a[0]), "r"(a[1]), "r"(a[2]), "r"(a[3]), "r"(b0), "r"(b1));
}

// ---------------------------------------------------------------------------
// Kernel 0: round W to tf32 (rna) once -> g_Wr. float4, 64 blocks.
// ---------------------------------------------------------------------------
__global__ __launch_bounds__(256) void wconv_kernel(const float4* __restrict__ W) {
    const int i = blockIdx.x * 256 + threadIdx.x;
    float4 v = W[i];
    uint4 u;
    u.x = f2tf32(v.x); u.y = f2tf32(v.y); u.z = f2tf32(v.z); u.w = f2tf32(v.w);
    ((uint4*)g_Wr)[i] = u;
}

// ---------------------------------------------------------------------------
// Kernel 1: h = x @ W.T + b (row 0 zeroed).
// 256 threads = 8 warps (4x2), block tile 128x128, warp tile 32x64.
// cp.async 3-stage pipeline (BK=8) + ldmatrix fragment loads.
// ---------------------------------------------------------------------------
__global__ __launch_bounds__(256, 2) void gemm_kernel(
    const float* __restrict__ x, const float* __restrict__ bias, int M)
{
    __shared__ uint32_t sA[STG][BM][RW];
    __shared__ uint32_t sB[STG][BN][RW];

    const int tid  = threadIdx.x;
    const int bn   = blockIdx.x * BN;   // grid.x = 2
    const int bm   = blockIdx.y * BM;
    const int warp = tid >> 5, lane = tid & 31;
    const int wr   = (warp >> 1) * 32;          // 0,32,64,96
    const int wc   = (warp & 1) * 64;           // 0,64
    const int g    = lane >> 2,  tg = lane & 3;
    const int sel  = lane >> 3,  r8 = lane & 7;

    const uint32_t sAu = smem_u32(sA), sBu = smem_u32(sB);

    // cp.async mapping: thread t -> row t>>1, 16B half t&1 (BK=8 -> 32B/row)
    const int crow = tid >> 1;
    const int chf  = tid & 1;
    const float* xsrc = x    + (size_t)(bm + crow) * DD + chf * 4;
    const float* wsrc = g_Wr + (size_t)(bn + crow) * DD + chf * 4;
    const uint32_t nbA = (bm + crow < M) ? 16u : 0u;
    const uint32_t dA  = sAu + (uint32_t)((crow * RW + chf * 4) * 4);
    const uint32_t dB  = sBu + (uint32_t)((crow * RW + chf * 4) * 4);

    // ldmatrix per-lane base addresses
    uint32_t aBase[2], bBase[4];
    #pragma unroll
    for (int mi = 0; mi < 2; mi++) {
        const int row = wr + mi * 16 + (sel & 1) * 8 + r8;
        aBase[mi] = sAu + (uint32_t)((row * RW + (sel >> 1) * 4) * 4);
    }
    #pragma unroll
    for (int p = 0; p < 4; p++) {
        const int row = wc + p * 16 + (sel >> 1) * 8 + r8;
        bBase[p] = sBu + (uint32_t)((row * RW + (sel & 1) * 4) * 4);
    }

    float acc[2][8][4];
    #pragma unroll
    for (int mi = 0; mi < 2; mi++)
        #pragma unroll
        for (int ni = 0; ni < 8; ni++)
            #pragma unroll
            for (int e = 0; e < 4; e++) acc[mi][ni][e] = 0.f;

    auto issue = [&](int c, int s) {
        const uint32_t ao = (uint32_t)(s * BM * RW * 4);
        const uint32_t bo = (uint32_t)(s * BN * RW * 4);
        const int ko = c * BK;
        cp16(dA + ao, xsrc + ko, nbA);
        cp16(dB + bo, wsrc + ko, 16u);
    };

    issue(0, 0); asm volatile("cp.async.commit_group;" ::: "memory");
    issue(1, 1); asm volatile("cp.async.commit_group;" ::: "memory");

    #pragma unroll 1
    for (int c = 0; c < NCH; c++) {
        const int s = c % STG;
        asm volatile("cp.async.wait_group 1;" ::: "memory");
        __syncthreads();
        if (c + 2 < NCH) issue(c + 2, (c + 2) % STG);
        asm volatile("cp.async.commit_group;" ::: "memory");

        const uint32_t ao = (uint32_t)(s * BM * RW * 4);
        const uint32_t bo = (uint32_t)(s * BN * RW * 4);
        uint32_t af[2][4], bf[4][4];
        ldsm4(af[0], aBase[0] + ao);
        ldsm4(af[1], aBase[1] + ao);
        #pragma unroll
        for (int p = 0; p < 4; p++) ldsm4(bf[p], bBase[p] + bo);
        #pragma unroll
        for (int mi = 0; mi < 2; mi++) {
            #pragma unroll
            for (int p = 0; p < 4; p++) {
                mma_tf32(acc[mi][p * 2 + 0], af[mi], bf[p][0], bf[p][1]);
                mma_tf32(acc[mi][p * 2 + 1], af[mi], bf[p][2], bf[p][3]);
            }
        }
    }

    // epilogue: + bias, zero row 0, store
    #pragma unroll
    for (int mi = 0; mi < 2; mi++) {
        #pragma unroll
        for (int ni = 0; ni < 8; ni++) {
            const int col = bn + wc + ni * 8 + tg * 2;
            const float b0 = bias[col];
            const float b1 = bias[col + 1];
            const int r0 = bm + wr + mi * 16 + g;
            const int r1 = r0 + 8;
            if (r0 < M) {
                const float v0 = (r0 == 0) ? 0.f : acc[mi][ni][0] + b0;
                const float v1 = (r0 == 0) ? 0.f : acc[mi][ni][1] + b1;
                g_h[(size_t)r0 * DD + col]     = v0;
                g_h[(size_t)r0 * DD + col + 1] = v1;
            }
            if (r1 < M) {
                g_h[(size_t)r1 * DD + col]     = acc[mi][ni][2] + b0;
                g_h[(size_t)r1 * DD + col + 1] = acc[mi][ni][3] + b1;
            }
        }
    }
}

// ---------------------------------------------------------------------------
// Kernel 2: out[i] = relu(h[i] + sum_k h[b_from_a[a_from_b[i][k]]])
// (unchanged — measured at its L1-wavefront/L2 floor)
// ---------------------------------------------------------------------------
__global__ __launch_bounds__(256) void agg_kernel(
    const int* __restrict__ b_from_a, const int* __restrict__ a_from_b,
    float* __restrict__ out, int M)
{
    const int atom = blockIdx.x * 4 + (threadIdx.x >> 6);
    if (atom >= M) return;
    const int t = threadIdx.x & 63;

    int idx[NB];
    #pragma unroll
    for (int k = 0; k < NB; k++) idx[k] = __ldg(a_from_b + (size_t)atom * NB + k);
    #pragma unroll
    for (int k = 0; k < NB; k++) idx[k] = __ldg(b_from_a + idx[k]);

    const float4* h4 = (const float4*)g_h;
    float4 acc = h4[(size_t)atom * (DD / 4) + t];

    #pragma unroll
    for (int k = 0; k < NB; k++) {
        float4 v = __ldg(h4 + (size_t)idx[k] * (DD / 4) + t);
        acc.x += v.x; acc.y += v.y; acc.z += v.z; acc.w += v.w;
    }

    acc.x = fmaxf(acc.x, 0.f);
    acc.y = fmaxf(acc.y, 0.f);
    acc.z = fmaxf(acc.z, 0.f);
    acc.w = fmaxf(acc.w, 0.f);
    ((float4*)out)[(size_t)atom * (DD / 4) + t] = acc;
}

// ---------------------------------------------------------------------------
// Launch: inputs per metadata order: x, W, b, b_from_a, a_from_b
// ---------------------------------------------------------------------------
extern "C" void kernel_launch(void* const* d_in, const int* in_sizes, int n_in,
                              void* d_out, int out_size) {
    const float* x        = (const float*)d_in[0];
    const float* W        = (const float*)d_in[1];
    const float* bias     = (const float*)d_in[2];
    const int*   b_from_a = (const int*)d_in[3];
    const int*   a_from_b = (const int*)d_in[4];
    float*       out      = (float*)d_out;

    const int M = in_sizes[0] / DD;   // 50000

    wconv_kernel<<<DD * DD / 1024, 256>>>((const float4*)W);

    dim3 ggrid(DD / BN, (M + BM - 1) / BM);   // (2, 391)
    gemm_kernel<<<ggrid, 256>>>(x, bias, M);

    agg_kernel<<<(M + 3) / 4, 256>>>(b_from_a, a_from_b, out, M);
}

// round 8
// speedup vs baseline: 1.0473x; 1.0473x over previous
#include <cuda_runtime.h>
#include <cuda_fp16.h>
#include <cstdint>

#define MAX_ATOMS 50000
#define DD 256
#define NB 16

#define BM 128
#define BN 128
#define BKH 32            // K chunk in halfs (64 B/row)
#define NCHH (DD / BKH)   // 8 chunks
#define RW 20             // 4B words per smem row (16 data + 4 pad; conflict-free)

// Scratch: h (fp32, row 0 zeroed), fp16 copies of x and W.
__device__ float  g_h[(size_t)MAX_ATOMS * DD];
__device__ __half g_xh[(size_t)MAX_ATOMS * DD];
__device__ __half g_Wh[DD * DD];

// ---------------------------------------------------------------------------
// helpers (sm_80-baseline features only — harness builds plain sm_103 PTX)
// ---------------------------------------------------------------------------
__device__ __forceinline__ uint32_t smem_u32(const void* p) {
    uint32_t a;
    asm("{ .reg .u64 t; cvta.to.shared.u64 t, %1; cvt.u32.u64 %0, t; }" : "=r"(a) : "l"(p));
    return a;
}
__device__ __forceinline__ void ldsm4(uint32_t r[4], uint32_t a) {
    asm volatile("ldmatrix.sync.aligned.m8n8.x4.shared.b16 {%0,%1,%2,%3}, [%4];"
                 : "=r"(r[0]), "=r"(r[1]), "=r"(r[2]), "=r"(r[3]) : "r"(a));
}
__device__ __forceinline__ void cp16(uint32_t dst, const void* src, uint32_t nbytes) {
    asm volatile("cp.async.cg.shared.global [%0], [%1], 16, %2;"
                 :: "r"(dst), "l"(src), "r"(nbytes));
}
__device__ __forceinline__ void mma_f16(float d[4], const uint32_t a[4],
                                        uint32_t b0, uint32_t b1) {
    asm volatile(
        "mma.sync.aligned.m16n8k16.row.col.f32.f16.f16.f32 "
        "{%0,%1,%2,%3}, {%4,%5,%6,%7}, {%8,%9}, {%0,%1,%2,%3};"
        : "+f"(d[0]), "+f"(d[1]), "+f"(d[2]), "+f"(d[3])
        : "r"(a[0]), "r"(a[1]), "r"(a[2]), "r"(a[3]), "r"(b0), "r"(b1));
}

// ---------------------------------------------------------------------------
// Kernel 0: convert x and W to fp16 (rn) once.
// ---------------------------------------------------------------------------
__global__ __launch_bounds__(256) void conv_kernel(
    const float4* __restrict__ x, const float4* __restrict__ W, int nx4)
{
    const int i = blockIdx.x * 256 + threadIdx.x;
    if (i < nx4) {
        float4 v = x[i];
        __half2* d = (__half2*)(g_xh + (size_t)i * 4);
        d[0] = __floats2half2_rn(v.x, v.y);
        d[1] = __floats2half2_rn(v.z, v.w);
    } else {
        const int j = i - nx4;
        if (j < DD * DD / 4) {
            float4 v = W[j];
            __half2* d = (__half2*)(g_Wh + (size_t)j * 4);
            d[0] = __floats2half2_rn(v.x, v.y);
            d[1] = __floats2half2_rn(v.z, v.w);
        }
    }
}

// ---------------------------------------------------------------------------
// Kernel 1: h = x @ W.T + b (row 0 zeroed), fp16 mma m16n8k16.
// 256 threads = 8 warps (4x2), block tile 128x128, warp tile 32x64.
// 2-stage cp.async pipeline, BK=32 halfs, 8 chunks.
// ---------------------------------------------------------------------------
__global__ __launch_bounds__(256, 2) void gemm_kernel(
    const float* __restrict__ bias, int M)
{
    __shared__ uint32_t sA[2][BM][RW];
    __shared__ uint32_t sB[2][BN][RW];

    const int tid  = threadIdx.x;
    const int bn   = blockIdx.x * BN;   // grid.x = 2
    const int bm   = blockIdx.y * BM;
    const int warp = tid >> 5, lane = tid & 31;
    const int wr   = (warp >> 1) * 32;
    const int wc   = (warp & 1) * 64;
    const int g    = lane >> 2,  tg = lane & 3;
    const int sel  = lane >> 3,  r8 = lane & 7;

    const uint32_t sAu = smem_u32(sA), sBu = smem_u32(sB);

    // cp.async mapping: thread t -> rows (t>>2) and (t>>2)+64, 16B chunk t&3.
    const int crow = tid >> 2;          // 0..63
    const int cch  = tid & 3;           // 16B chunk within 64B row
    const __half* xs0 = g_xh + (size_t)(bm + crow)      * DD + cch * 8;
    const __half* xs1 = g_xh + (size_t)(bm + crow + 64) * DD + cch * 8;
    const __half* ws0 = g_Wh + (size_t)(bn + crow)      * DD + cch * 8;
    const __half* ws1 = g_Wh + (size_t)(bn + crow + 64) * DD + cch * 8;
    const uint32_t nb0 = (bm + crow      < M) ? 16u : 0u;
    const uint32_t nb1 = (bm + crow + 64 < M) ? 16u : 0u;
    const uint32_t dA0 = sAu + (uint32_t)((crow       * RW + cch * 4) * 4);
    const uint32_t dA1 = sAu + (uint32_t)(((crow + 64) * RW + cch * 4) * 4);
    const uint32_t dB0 = sBu + (uint32_t)((crow       * RW + cch * 4) * 4);
    const uint32_t dB1 = sBu + (uint32_t)(((crow + 64) * RW + cch * 4) * 4);

    // ldmatrix per-lane base addresses (16B chunk = 4 words)
    uint32_t aBase[2], bBase[4];
    #pragma unroll
    for (int mi = 0; mi < 2; mi++) {
        const int row = wr + mi * 16 + (sel & 1) * 8 + r8;
        aBase[mi] = sAu + (uint32_t)((row * RW + (sel >> 1) * 4) * 4);
    }
    #pragma unroll
    for (int p = 0; p < 4; p++) {
        const int row = wc + p * 16 + (sel & 1) * 8 + r8;
        bBase[p] = sBu + (uint32_t)((row * RW + (sel >> 1) * 4) * 4);
    }

    float acc[2][8][4];
    #pragma unroll
    for (int mi = 0; mi < 2; mi++)
        #pragma unroll
        for (int ni = 0; ni < 8; ni++)
            #pragma unroll
            for (int e = 0; e < 4; e++) acc[mi][ni][e] = 0.f;

    auto issue = [&](int c, int s) {
        const uint32_t ao = (uint32_t)(s * BM * RW * 4);
        const uint32_t bo = (uint32_t)(s * BN * RW * 4);
        const int ko = c * BKH;
        cp16(dA0 + ao, xs0 + ko, nb0);
        cp16(dA1 + ao, xs1 + ko, nb1);
        cp16(dB0 + bo, ws0 + ko, 16u);
        cp16(dB1 + bo, ws1 + ko, 16u);
    };

    issue(0, 0); asm volatile("cp.async.commit_group;" ::: "memory");

    #pragma unroll 1
    for (int c = 0; c < NCHH; c++) {
        const int s = c & 1;
        if (c + 1 < NCHH) {
            issue(c + 1, (c + 1) & 1);
            asm volatile("cp.async.commit_group;" ::: "memory");
            asm volatile("cp.async.wait_group 1;" ::: "memory");
        } else {
            asm volatile("cp.async.wait_group 0;" ::: "memory");
        }
        __syncthreads();

        const uint32_t ao = (uint32_t)(s * BM * RW * 4);
        const uint32_t bo = (uint32_t)(s * BN * RW * 4);
        #pragma unroll
        for (int ks = 0; ks < 2; ks++) {           // two k16 steps per chunk
            const uint32_t kb = (uint32_t)(ks * 32);   // 2 chunks = 32 B
            uint32_t af[2][4], bf[4][4];
            ldsm4(af[0], aBase[0] + ao + kb);
            ldsm4(af[1], aBase[1] + ao + kb);
            #pragma unroll
            for (int p = 0; p < 4; p++) ldsm4(bf[p], bBase[p] + bo + kb);
            #pragma unroll
            for (int mi = 0; mi < 2; mi++) {
                #pragma unroll
                for (int p = 0; p < 4; p++) {
                    mma_f16(acc[mi][p * 2 + 0], af[mi], bf[p][0], bf[p][2]);
                    mma_f16(acc[mi][p * 2 + 1], af[mi], bf[p][1], bf[p][3]);
                }
            }
        }
        __syncthreads();   // buffer s is free for chunk c+2's issue next iter
    }

    // epilogue: + bias, zero row 0, store
    #pragma unroll
    for (int mi = 0; mi < 2; mi++) {
        #pragma unroll
        for (int ni = 0; ni < 8; ni++) {
            const int col = bn + wc + ni * 8 + tg * 2;
            const float b0 = bias[col];
            const float b1 = bias[col + 1];
            const int r0 = bm + wr + mi * 16 + g;
            const int r1 = r0 + 8;
            if (r0 < M) {
                const float v0 = (r0 == 0) ? 0.f : acc[mi][ni][0] + b0;
                const float v1 = (r0 == 0) ? 0.f : acc[mi][ni][1] + b1;
                g_h[(size_t)r0 * DD + col]     = v0;
                g_h[(size_t)r0 * DD + col + 1] = v1;
            }
            if (r1 < M) {
                g_h[(size_t)r1 * DD + col]     = acc[mi][ni][2] + b0;
                g_h[(size_t)r1 * DD + col + 1] = acc[mi][ni][3] + b1;
            }
        }
    }
}

// ---------------------------------------------------------------------------
// Kernel 2: out[i] = relu(h[i] + sum_k h[b_from_a[a_from_b[i][k]]])
// (unchanged — measured at its L1-wavefront/L2 floor)
// ---------------------------------------------------------------------------
__global__ __launch_bounds__(256) void agg_kernel(
    const int* __restrict__ b_from_a, const int* __restrict__ a_from_b,
    float* __restrict__ out, int M)
{
    const int atom = blockIdx.x * 4 + (threadIdx.x >> 6);
    if (atom >= M) return;
    const int t = threadIdx.x & 63;

    int idx[NB];
    #pragma unroll
    for (int k = 0; k < NB; k++) idx[k] = __ldg(a_from_b + (size_t)atom * NB + k);
    #pragma unroll
    for (int k = 0; k < NB; k++) idx[k] = __ldg(b_from_a + idx[k]);

    const float4* h4 = (const float4*)g_h;
    float4 acc = h4[(size_t)atom * (DD / 4) + t];

    #pragma unroll
    for (int k = 0; k < NB; k++) {
        float4 v = __ldg(h4 + (size_t)idx[k] * (DD / 4) + t);
        acc.x += v.x; acc.y += v.y; acc.z += v.z; acc.w += v.w;
    }

    acc.x = fmaxf(acc.x, 0.f);
    acc.y = fmaxf(acc.y, 0.f);
    acc.z = fmaxf(acc.z, 0.f);
    acc.w = fmaxf(acc.w, 0.f);
    ((float4*)out)[(size_t)atom * (DD / 4) + t] = acc;
}

// ---------------------------------------------------------------------------
// Launch: inputs per metadata order: x, W, b, b_from_a, a_from_b
// ---------------------------------------------------------------------------
extern "C" void kernel_launch(void* const* d_in, const int* in_sizes, int n_in,
                              void* d_out, int out_size) {
    const float* x        = (const float*)d_in[0];
    const float* W        = (const float*)d_in[1];
    const float* bias     = (const float*)d_in[2];
    const int*   b_from_a = (const int*)d_in[3];
    const int*   a_from_b = (const int*)d_in[4];
    float*       out      = (float*)d_out;

    const int M = in_sizes[0] / DD;   // 50000
    const int nx4 = in_sizes[0] / 4;

    const int ctot = nx4 + DD * DD / 4;
    conv_kernel<<<(ctot + 255) / 256, 256>>>((const float4*)x, (const float4*)W, nx4);

    dim3 ggrid(DD / BN, (M + BM - 1) / BM);   // (2, 391)
    gemm_kernel<<<ggrid, 256>>>(bias, M);

    agg_kernel<<<(M + 3) / 4, 256>>>(b_from_a, a_from_b, out, M);
}

// round 9
// speedup vs baseline: 1.3887x; 1.3260x over previous
#include <cuda_runtime.h>
#include <cuda_fp16.h>
#include <cstdint>

#define MAX_ATOMS 50000
#define DD 256
#define NB 16

#define BM 128
#define BN 128
#define BKH 32            // K chunk in halfs (64 B/row)
#define NCHH (DD / BKH)   // 8 chunks
#define RW 20             // 4B words per smem row (16 data + 4 pad; conflict-free)

// Scratch: fp16 h (row 0 zeroed), fp16 copies of x and W.
__device__ __half g_hh[(size_t)MAX_ATOMS * DD];
__device__ __half g_xh[(size_t)MAX_ATOMS * DD];
__device__ __half g_Wh[DD * DD];

// ---------------------------------------------------------------------------
// helpers (sm_80-baseline features only — harness builds plain sm_103 PTX)
// ---------------------------------------------------------------------------
__device__ __forceinline__ uint32_t smem_u32(const void* p) {
    uint32_t a;
    asm("{ .reg .u64 t; cvta.to.shared.u64 t, %1; cvt.u32.u64 %0, t; }" : "=r"(a) : "l"(p));
    return a;
}
__device__ __forceinline__ void ldsm4(uint32_t r[4], uint32_t a) {
    asm volatile("ldmatrix.sync.aligned.m8n8.x4.shared.b16 {%0,%1,%2,%3}, [%4];"
                 : "=r"(r[0]), "=r"(r[1]), "=r"(r[2]), "=r"(r[3]) : "r"(a));
}
__device__ __forceinline__ void cp16(uint32_t dst, const void* src, uint32_t nbytes) {
    asm volatile("cp.async.cg.shared.global [%0], [%1], 16, %2;"
                 :: "r"(dst), "l"(src), "r"(nbytes));
}
__device__ __forceinline__ void mma_f16(float d[4], const uint32_t a[4],
                                        uint32_t b0, uint32_t b1) {
    asm volatile(
        "mma.sync.aligned.m16n8k16.row.col.f32.f16.f16.f32 "
        "{%0,%1,%2,%3}, {%4,%5,%6,%7}, {%8,%9}, {%0,%1,%2,%3};"
        : "+f"(d[0]), "+f"(d[1]), "+f"(d[2]), "+f"(d[3])
        : "r"(a[0]), "r"(a[1]), "r"(a[2]), "r"(a[3]), "r"(b0), "r"(b1));
}

// ---------------------------------------------------------------------------
// Kernel 0: convert x and W to fp16 (rn) once.
// ---------------------------------------------------------------------------
__global__ __launch_bounds__(256) void conv_kernel(
    const float4* __restrict__ x, const float4* __restrict__ W, int nx4)
{
    const int i = blockIdx.x * 256 + threadIdx.x;
    if (i < nx4) {
        float4 v = x[i];
        __half2* d = (__half2*)(g_xh + (size_t)i * 4);
        d[0] = __floats2half2_rn(v.x, v.y);
        d[1] = __floats2half2_rn(v.z, v.w);
    } else {
        const int j = i - nx4;
        if (j < DD * DD / 4) {
            float4 v = W[j];
            __half2* d = (__half2*)(g_Wh + (size_t)j * 4);
            d[0] = __floats2half2_rn(v.x, v.y);
            d[1] = __floats2half2_rn(v.z, v.w);
        }
    }
}

// ---------------------------------------------------------------------------
// Kernel 1: h = x @ W.T + b (row 0 zeroed), fp16 mma m16n8k16 -> fp16 h.
// 256 threads = 8 warps (4x2), block tile 128x128, warp tile 32x64.
// 2-stage cp.async pipeline, BK=32 halfs, 8 chunks.
// ---------------------------------------------------------------------------
__global__ __launch_bounds__(256, 2) void gemm_kernel(
    const float* __restrict__ bias, int M)
{
    __shared__ uint32_t sA[2][BM][RW];
    __shared__ uint32_t sB[2][BN][RW];

    const int tid  = threadIdx.x;
    const int bn   = blockIdx.x * BN;   // grid.x = 2
    const int bm   = blockIdx.y * BM;
    const int warp = tid >> 5, lane = tid & 31;
    const int wr   = (warp >> 1) * 32;
    const int wc   = (warp & 1) * 64;
    const int g    = lane >> 2,  tg = lane & 3;
    const int sel  = lane >> 3,  r8 = lane & 7;

    const uint32_t sAu = smem_u32(sA), sBu = smem_u32(sB);

    // cp.async mapping: thread t -> rows (t>>2) and (t>>2)+64, 16B chunk t&3.
    const int crow = tid >> 2;          // 0..63
    const int cch  = tid & 3;           // 16B chunk within 64B row
    const __half* xs0 = g_xh + (size_t)(bm + crow)      * DD + cch * 8;
    const __half* xs1 = g_xh + (size_t)(bm + crow + 64) * DD + cch * 8;
    const __half* ws0 = g_Wh + (size_t)(bn + crow)      * DD + cch * 8;
    const __half* ws1 = g_Wh + (size_t)(bn + crow + 64) * DD + cch * 8;
    const uint32_t nb0 = (bm + crow      < M) ? 16u : 0u;
    const uint32_t nb1 = (bm + crow + 64 < M) ? 16u : 0u;
    const uint32_t dA0 = sAu + (uint32_t)((crow       * RW + cch * 4) * 4);
    const uint32_t dA1 = sAu + (uint32_t)(((crow + 64) * RW + cch * 4) * 4);
    const uint32_t dB0 = sBu + (uint32_t)((crow       * RW + cch * 4) * 4);
    const uint32_t dB1 = sBu + (uint32_t)(((crow + 64) * RW + cch * 4) * 4);

    // ldmatrix per-lane base addresses (16B chunk = 4 words)
    uint32_t aBase[2], bBase[4];
    #pragma unroll
    for (int mi = 0; mi < 2; mi++) {
        const int row = wr + mi * 16 + (sel & 1) * 8 + r8;
        aBase[mi] = sAu + (uint32_t)((row * RW + (sel >> 1) * 4) * 4);
    }
    #pragma unroll
    for (int p = 0; p < 4; p++) {
        const int row = wc + p * 16 + (sel & 1) * 8 + r8;
        bBase[p] = sBu + (uint32_t)((row * RW + (sel >> 1) * 4) * 4);
    }

    float acc[2][8][4];
    #pragma unroll
    for (int mi = 0; mi < 2; mi++)
        #pragma unroll
        for (int ni = 0; ni < 8; ni++)
            #pragma unroll
            for (int e = 0; e < 4; e++) acc[mi][ni][e] = 0.f;

    auto issue = [&](int c, int s) {
        const uint32_t ao = (uint32_t)(s * BM * RW * 4);
        const uint32_t bo = (uint32_t)(s * BN * RW * 4);
        const int ko = c * BKH;
        cp16(dA0 + ao, xs0 + ko, nb0);
        cp16(dA1 + ao, xs1 + ko, nb1);
        cp16(dB0 + bo, ws0 + ko, 16u);
        cp16(dB1 + bo, ws1 + ko, 16u);
    };

    issue(0, 0); asm volatile("cp.async.commit_group;" ::: "memory");

    #pragma unroll 1
    for (int c = 0; c < NCHH; c++) {
        const int s = c & 1;
        if (c + 1 < NCHH) {
            issue(c + 1, (c + 1) & 1);
            asm volatile("cp.async.commit_group;" ::: "memory");
            asm volatile("cp.async.wait_group 1;" ::: "memory");
        } else {
            asm volatile("cp.async.wait_group 0;" ::: "memory");
        }
        __syncthreads();

        const uint32_t ao = (uint32_t)(s * BM * RW * 4);
        const uint32_t bo = (uint32_t)(s * BN * RW * 4);
        #pragma unroll
        for (int ks = 0; ks < 2; ks++) {           // two k16 steps per chunk
            const uint32_t kb = (uint32_t)(ks * 32);
            uint32_t af[2][4], bf[4][4];
            ldsm4(af[0], aBase[0] + ao + kb);
            ldsm4(af[1], aBase[1] + ao + kb);
            #pragma unroll
            for (int p = 0; p < 4; p++) ldsm4(bf[p], bBase[p] + bo + kb);
            #pragma unroll
            for (int mi = 0; mi < 2; mi++) {
                #pragma unroll
                for (int p = 0; p < 4; p++) {
                    mma_f16(acc[mi][p * 2 + 0], af[mi], bf[p][0], bf[p][2]);
                    mma_f16(acc[mi][p * 2 + 1], af[mi], bf[p][1], bf[p][3]);
                }
            }
        }
        __syncthreads();
    }

    // epilogue: + bias, zero row 0, store fp16 (half2 per acc pair)
    #pragma unroll
    for (int mi = 0; mi < 2; mi++) {
        #pragma unroll
        for (int ni = 0; ni < 8; ni++) {
            const int col = bn + wc + ni * 8 + tg * 2;
            const float b0 = bias[col];
            const float b1 = bias[col + 1];
            const int r0 = bm + wr + mi * 16 + g;
            const int r1 = r0 + 8;
            if (r0 < M) {
                const float v0 = (r0 == 0) ? 0.f : acc[mi][ni][0] + b0;
                const float v1 = (r0 == 0) ? 0.f : acc[mi][ni][1] + b1;
                *(__half2*)(g_hh + (size_t)r0 * DD + col) = __floats2half2_rn(v0, v1);
            }
            if (r1 < M) {
                *(__half2*)(g_hh + (size_t)r1 * DD + col) =
                    __floats2half2_rn(acc[mi][ni][2] + b0, acc[mi][ni][3] + b1);
            }
        }
    }
}

// ---------------------------------------------------------------------------
// Kernel 2: out[i] = relu(h[i] + sum_k h[b_from_a[a_from_b[i][k]]])
// One warp per atom; lane covers 8 halfs (16B). fp32 accumulation.
// ---------------------------------------------------------------------------
__global__ __launch_bounds__(256) void agg_kernel(
    const int* __restrict__ b_from_a, const int* __restrict__ a_from_b,
    float* __restrict__ out, int M)
{
    const int atom = blockIdx.x * 8 + (threadIdx.x >> 5);
    if (atom >= M) return;
    const int lane = threadIdx.x & 31;

    // lanes 0..15 fetch the two-level index; distribute via shfl
    int aidx = 0;
    if (lane < NB) {
        const int bond = __ldg(a_from_b + (size_t)atom * NB + lane);
        aidx = __ldg(b_from_a + bond);
    }

    const uint4* h16 = (const uint4*)g_hh;    // 16B = 8 halfs; row = 32 uint4
    uint4 self = __ldg(h16 + (size_t)atom * 32 + lane);

    float acc[8];
    {
        const __half2* p = (const __half2*)&self;
        #pragma unroll
        for (int j = 0; j < 4; j++) {
            float2 f = __half22float2(p[j]);
            acc[j * 2] = f.x; acc[j * 2 + 1] = f.y;
        }
    }

    #pragma unroll
    for (int k = 0; k < NB; k++) {
        const int idx = __shfl_sync(0xFFFFFFFFu, aidx, k);
        uint4 v = __ldg(h16 + (size_t)idx * 32 + lane);
        const __half2* p = (const __half2*)&v;
        #pragma unroll
        for (int j = 0; j < 4; j++) {
            float2 f = __half22float2(p[j]);
            acc[j * 2] += f.x; acc[j * 2 + 1] += f.y;
        }
    }

    float4 o0, o1;
    o0.x = fmaxf(acc[0], 0.f); o0.y = fmaxf(acc[1], 0.f);
    o0.z = fmaxf(acc[2], 0.f); o0.w = fmaxf(acc[3], 0.f);
    o1.x = fmaxf(acc[4], 0.f); o1.y = fmaxf(acc[5], 0.f);
    o1.z = fmaxf(acc[6], 0.f); o1.w = fmaxf(acc[7], 0.f);
    float4* op = (float4*)(out + (size_t)atom * DD + lane * 8);
    op[0] = o0;
    op[1] = o1;
}

// ---------------------------------------------------------------------------
// Launch: inputs per metadata order: x, W, b, b_from_a, a_from_b
// ---------------------------------------------------------------------------
extern "C" void kernel_launch(void* const* d_in, const int* in_sizes, int n_in,
                              void* d_out, int out_size) {
    const float* x        = (const float*)d_in[0];
    const float* W        = (const float*)d_in[1];
    const float* bias     = (const float*)d_in[2];
    const int*   b_from_a = (const int*)d_in[3];
    const int*   a_from_b = (const int*)d_in[4];
    float*       out      = (float*)d_out;

    const int M = in_sizes[0] / DD;   // 50000
    const int nx4 = in_sizes[0] / 4;

    const int ctot = nx4 + DD * DD / 4;
    conv_kernel<<<(ctot + 255) / 256, 256>>>((const float4*)x, (const float4*)W, nx4);

    dim3 ggrid(DD / BN, (M + BM - 1) / BM);   // (2, 391)
    gemm_kernel<<<ggrid, 256>>>(bias, M);

    agg_kernel<<<(M + 7) / 8, 256>>>(b_from_a, a_from_b, out, M);
}